// round 1
// baseline (speedup 1.0000x reference)
#include <cuda_runtime.h>
#include <math.h>

#define B_N 4096
#define D_N 2048
#define C_N 64

// -------- scratch (static device globals; no allocation) --------
__device__ float g_xnorm[B_N * D_N];                 // 32 MB
__device__ float g_expS[(size_t)B_N * B_N];          // 64 MB
__device__ float g_inv[B_N];
__device__ float g_keep[B_N];
__device__ float g_contrib[B_N];
__device__ float g_R[B_N * D_N];                     // 32 MB

// -------- K0: per-sample class-derived scalars --------
__global__ void k_prep(const int* __restrict__ y, const float* __restrict__ c,
                       const int* __restrict__ fs) {
    int i = blockIdx.x * blockDim.x + threadIdx.x;
    if (i < B_N) {
        int cls = y[i];
        g_contrib[i] = c[cls];
        g_keep[i] = fs[cls] ? 0.0f : 1.0f;
    }
}

// -------- K1: LayerNorm row, then / sqrt(D) --------
__global__ __launch_bounds__(256) void k_lnorm(const float* __restrict__ x) {
    int row = blockIdx.x;
    const float* xr = x + (size_t)row * D_N;
    float s = 0.f, s2 = 0.f;
    for (int d = threadIdx.x; d < D_N; d += 256) {
        float v = xr[d];
        s += v; s2 += v * v;
    }
    __shared__ float sh[34];
    #pragma unroll
    for (int o = 16; o > 0; o >>= 1) {
        s  += __shfl_down_sync(0xffffffffu, s, o);
        s2 += __shfl_down_sync(0xffffffffu, s2, o);
    }
    int w = threadIdx.x >> 5, l = threadIdx.x & 31;
    if (l == 0) { sh[w] = s; sh[8 + w] = s2; }
    __syncthreads();
    if (threadIdx.x == 0) {
        float S = 0.f, S2 = 0.f;
        #pragma unroll
        for (int i = 0; i < 8; i++) { S += sh[i]; S2 += sh[8 + i]; }
        float mu = S / (float)D_N;
        float var = S2 / (float)D_N - mu * mu;
        sh[32] = mu;
        sh[33] = rsqrtf(var + 1e-5f) * rsqrtf((float)D_N);
    }
    __syncthreads();
    float mu = sh[32], sc = sh[33];
    float* xo = g_xnorm + (size_t)row * D_N;
    for (int d = threadIdx.x; d < D_N; d += 256)
        xo[d] = (xr[d] - mu) * sc;
}

// -------- K2: S = Xn * Xn^T, fused mask + exp --------
// 128x128 block tile, 8x8 per-thread microtile, K-tile 8.
#define BT 128
#define KT 8
#define LDS_PAD 132  // 128 + 4, keeps float4 alignment, dodges store conflicts

__global__ __launch_bounds__(256) void k_gemm1() {
    __shared__ float As[KT][LDS_PAD];
    __shared__ float Bs[KT][LDS_PAD];
    const int bm = blockIdx.y, bn = blockIdx.x;
    const int t = threadIdx.x;
    const int tx = t & 15, ty = t >> 4;

    float acc[8][8];
    #pragma unroll
    for (int i = 0; i < 8; i++)
        #pragma unroll
        for (int j = 0; j < 8; j++) acc[i][j] = 0.f;

    const int lr = t >> 1;          // 0..127 (tile row)
    const int lc = (t & 1) * 4;     // 0 or 4 (k offset)
    const float* Ag = g_xnorm + (size_t)(bm * BT + lr) * D_N + lc;
    const float* Bg = g_xnorm + (size_t)(bn * BT + lr) * D_N + lc;

    for (int k0 = 0; k0 < D_N; k0 += KT) {
        float4 av = *(const float4*)(Ag + k0);
        float4 bv = *(const float4*)(Bg + k0);
        __syncthreads();
        As[lc + 0][lr] = av.x; As[lc + 1][lr] = av.y;
        As[lc + 2][lr] = av.z; As[lc + 3][lr] = av.w;
        Bs[lc + 0][lr] = bv.x; Bs[lc + 1][lr] = bv.y;
        Bs[lc + 2][lr] = bv.z; Bs[lc + 3][lr] = bv.w;
        __syncthreads();
        #pragma unroll
        for (int kk = 0; kk < KT; kk++) {
            float a[8], b[8];
            *(float4*)(a)     = *(const float4*)&As[kk][ty * 8];
            *(float4*)(a + 4) = *(const float4*)&As[kk][ty * 8 + 4];
            *(float4*)(b)     = *(const float4*)&Bs[kk][tx * 8];
            *(float4*)(b + 4) = *(const float4*)&Bs[kk][tx * 8 + 4];
            #pragma unroll
            for (int i = 0; i < 8; i++)
                #pragma unroll
                for (int j = 0; j < 8; j++)
                    acc[i][j] += a[i] * b[j];
        }
    }

    const int gi0 = bm * BT + ty * 8;
    const int gj0 = bn * BT + tx * 8;
    float kp[8];
    #pragma unroll
    for (int j = 0; j < 8; j++) kp[j] = g_keep[gj0 + j];

    #pragma unroll
    for (int i = 0; i < 8; i++) {
        int gi = gi0 + i;
        float* orow = g_expS + (size_t)gi * B_N + gj0;
        float v[8];
        #pragma unroll
        for (int j = 0; j < 8; j++) {
            float w = (gj0 + j == gi) ? 0.f : kp[j];
            v[j] = w * __expf(acc[i][j]);
        }
        *(float4*)(orow)     = *(const float4*)(v);
        *(float4*)(orow + 4) = *(const float4*)(v + 4);
    }
}

// -------- K3: row sums of expS -> reciprocal --------
__global__ __launch_bounds__(256) void k_rowsum() {
    int row = blockIdx.x;
    const float* r = g_expS + (size_t)row * B_N;
    float s = 0.f;
    for (int j = threadIdx.x; j < B_N; j += 256) s += r[j];
    __shared__ float sh[8];
    #pragma unroll
    for (int o = 16; o > 0; o >>= 1) s += __shfl_down_sync(0xffffffffu, s, o);
    int w = threadIdx.x >> 5, l = threadIdx.x & 31;
    if (l == 0) sh[w] = s;
    __syncthreads();
    if (threadIdx.x == 0) {
        float S = 0.f;
        #pragma unroll
        for (int i = 0; i < 8; i++) S += sh[i];
        g_inv[row] = 1.0f / S;
    }
}

// -------- K4: recon = expS @ x, fused softmax-normalize + residual blend --------
// M=4096 (rows of expS), N=2048 (cols of x), K=4096.
__global__ __launch_bounds__(256) void k_gemm2(const float* __restrict__ x) {
    __shared__ float As[KT][LDS_PAD];
    __shared__ float Bs[KT][LDS_PAD];
    const int bm = blockIdx.y, bn = blockIdx.x;
    const int t = threadIdx.x;
    const int tx = t & 15, ty = t >> 4;

    float acc[8][8];
    #pragma unroll
    for (int i = 0; i < 8; i++)
        #pragma unroll
        for (int j = 0; j < 8; j++) acc[i][j] = 0.f;

    const int lr = t >> 1;
    const int lc = (t & 1) * 4;
    const float* Ag = g_expS + (size_t)(bm * BT + lr) * B_N + lc;

    const int kr = t >> 5;           // 0..7 (k row of B tile)
    const int cc = (t & 31) * 4;     // 0..124 (col offset)
    const float* Bg = x + (size_t)kr * D_N + bn * BT + cc;

    for (int k0 = 0; k0 < B_N; k0 += KT) {
        float4 av = *(const float4*)(Ag + k0);
        float4 bv = *(const float4*)(Bg + (size_t)k0 * D_N);
        __syncthreads();
        As[lc + 0][lr] = av.x; As[lc + 1][lr] = av.y;
        As[lc + 2][lr] = av.z; As[lc + 3][lr] = av.w;
        *(float4*)&Bs[kr][cc] = bv;
        __syncthreads();
        #pragma unroll
        for (int kk = 0; kk < KT; kk++) {
            float a[8], b[8];
            *(float4*)(a)     = *(const float4*)&As[kk][ty * 8];
            *(float4*)(a + 4) = *(const float4*)&As[kk][ty * 8 + 4];
            *(float4*)(b)     = *(const float4*)&Bs[kk][tx * 8];
            *(float4*)(b + 4) = *(const float4*)&Bs[kk][tx * 8 + 4];
            #pragma unroll
            for (int i = 0; i < 8; i++)
                #pragma unroll
                for (int j = 0; j < 8; j++)
                    acc[i][j] += a[i] * b[j];
        }
    }

    const int gi0 = bm * BT + ty * 8;
    const int gj0 = bn * BT + tx * 8;
    #pragma unroll
    for (int i = 0; i < 8; i++) {
        int gi = gi0 + i;
        float s1 = g_inv[gi] * g_contrib[gi];     // softmax normalize * contrib
        float s2 = 1.0f - g_contrib[gi];          // residual weight
        const float* xrow = x + (size_t)gi * D_N + gj0;
        float* rrow = g_R + (size_t)gi * D_N + gj0;
        float4 x0 = *(const float4*)(xrow);
        float4 x1 = *(const float4*)(xrow + 4);
        float v[8];
        v[0] = acc[i][0] * s1 + x0.x * s2; v[1] = acc[i][1] * s1 + x0.y * s2;
        v[2] = acc[i][2] * s1 + x0.z * s2; v[3] = acc[i][3] * s1 + x0.w * s2;
        v[4] = acc[i][4] * s1 + x1.x * s2; v[5] = acc[i][5] * s1 + x1.y * s2;
        v[6] = acc[i][6] * s1 + x1.z * s2; v[7] = acc[i][7] * s1 + x1.w * s2;
        *(float4*)(rrow)     = *(const float4*)(v);
        *(float4*)(rrow + 4) = *(const float4*)(v + 4);
    }
}

// -------- K5: x_mix = a*R + (1-a)*R[beta] (float4) --------
__global__ __launch_bounds__(256) void k_mixx(const float* __restrict__ alpha,
                                              const int* __restrict__ beta,
                                              float* __restrict__ out) {
    int idx = blockIdx.x * blockDim.x + threadIdx.x;   // over B*D/4
    const int nd4 = D_N / 4;
    if (idx < B_N * nd4) {
        int i = idx / nd4;
        int d4 = idx - i * nd4;
        float a = alpha[i];
        float na = 1.0f - a;
        int bi = beta[i];
        const float4* R4 = (const float4*)g_R;
        float4 r1 = R4[(size_t)i * nd4 + d4];
        float4 r2 = R4[(size_t)bi * nd4 + d4];
        float4 o;
        o.x = a * r1.x + na * r2.x;
        o.y = a * r1.y + na * r2.y;
        o.z = a * r1.z + na * r2.z;
        o.w = a * r1.w + na * r2.w;
        ((float4*)out)[idx] = o;
    }
}

// -------- K6: y_mix one-hot blend --------
__global__ void k_mixy(const float* __restrict__ alpha,
                       const int* __restrict__ beta,
                       const int* __restrict__ y,
                       float* __restrict__ out) {
    int idx = blockIdx.x * blockDim.x + threadIdx.x;   // over B*C
    if (idx < B_N * C_N) {
        int i = idx / C_N;
        int k = idx - i * C_N;
        float a = alpha[i];
        int bi = beta[i];
        float v = a * (k == y[i] ? 1.0f : 0.0f) + (1.0f - a) * (k == y[bi] ? 1.0f : 0.0f);
        out[(size_t)B_N * D_N + idx] = v;
    }
}

extern "C" void kernel_launch(void* const* d_in, const int* in_sizes, int n_in,
                              void* d_out, int out_size) {
    const float* x     = (const float*)d_in[0];
    const int*   y     = (const int*)  d_in[1];
    const float* alpha = (const float*)d_in[2];
    const int*   beta  = (const int*)  d_in[3];
    const float* c     = (const float*)d_in[4];
    const int*   fs    = (const int*)  d_in[5];
    float* out = (float*)d_out;

    k_prep<<<(B_N + 255) / 256, 256>>>(y, c, fs);
    k_lnorm<<<B_N, 256>>>(x);
    k_gemm1<<<dim3(B_N / BT, B_N / BT), 256>>>();
    k_rowsum<<<B_N, 256>>>();
    k_gemm2<<<dim3(D_N / BT, B_N / BT), 256>>>(x);
    k_mixx<<<(B_N * (D_N / 4) + 255) / 256, 256>>>(alpha, beta, out);
    k_mixy<<<(B_N * C_N + 255) / 256, 256>>>(alpha, beta, y, out);
}

// round 4
// speedup vs baseline: 7.0236x; 7.0236x over previous
#include <cuda_runtime.h>
#include <cuda_bf16.h>
#include <stdint.h>
#include <math.h>

#define B_N 4096
#define D_N 2048
#define C_N 64

#define BT 128            // CTA tile M = N = 128
#define BKS 64            // K per stage (bf16 elems) = 128 bytes per row
#define STAGES 3
#define A_TILE_B (BT*128)               // 16384 bytes
#define STAGE_B  (2*A_TILE_B)           // 32768 bytes
#define SMEM_TOTAL (1024 + STAGES*STAGE_B)   // 99328

// ---------------- scratch (static device globals) ----------------
__device__ __align__(128) __nv_bfloat16 g_xbf[B_N * D_N];            // 16 MB
__device__ __align__(128) __nv_bfloat16 g_xT[D_N * B_N];             // 16 MB
__device__ __align__(128) __nv_bfloat16 g_expSbf[(size_t)B_N * B_N]; // 32 MB
__device__ __align__(128) float g_R[B_N * D_N];                      // 32 MB
__device__ float g_rowsum[B_N];
__device__ float g_inv[B_N];
__device__ float g_keep[B_N];
__device__ float g_contrib[B_N];

// ---------------- PTX helpers (all non-arch-specific: sm_80+ ISA) ----------------
__device__ __forceinline__ uint32_t smem_u32(const void* p) {
    uint32_t a;
    asm("{ .reg .u64 t; cvta.to.shared.u64 t, %1; cvt.u32.u64 %0, t; }" : "=r"(a) : "l"(p));
    return a;
}
__device__ __forceinline__ void cp16(uint32_t s, const void* g) {
    asm volatile("cp.async.cg.shared.global [%0], [%1], 16;" :: "r"(s), "l"(g));
}
__device__ __forceinline__ void cp_commit() { asm volatile("cp.async.commit_group;"); }
__device__ __forceinline__ void cp_wait1()  { asm volatile("cp.async.wait_group 1;"); }

__device__ __forceinline__ void ldsm4(uint32_t* r, uint32_t addr) {
    asm volatile("ldmatrix.sync.aligned.m8n8.x4.shared.b16 {%0,%1,%2,%3}, [%4];"
        : "=r"(r[0]), "=r"(r[1]), "=r"(r[2]), "=r"(r[3]) : "r"(addr));
}
__device__ __forceinline__ void mma_bf16(float* c, const uint32_t* a, uint32_t b0, uint32_t b1) {
    asm volatile(
        "mma.sync.aligned.m16n8k16.row.col.f32.bf16.bf16.f32 "
        "{%0,%1,%2,%3}, {%4,%5,%6,%7}, {%8,%9}, {%0,%1,%2,%3};"
        : "+f"(c[0]), "+f"(c[1]), "+f"(c[2]), "+f"(c[3])
        : "r"(a[0]), "r"(a[1]), "r"(a[2]), "r"(a[3]), "r"(b0), "r"(b1));
}

// ---------------- small kernels ----------------
__global__ void k_prep(const int* __restrict__ y, const float* __restrict__ c,
                       const int* __restrict__ fs) {
    int i = blockIdx.x * blockDim.x + threadIdx.x;
    if (i < B_N) {
        int cls = y[i];
        g_contrib[i] = c[cls];
        g_keep[i] = fs[cls] ? 0.0f : 1.0f;
        g_rowsum[i] = 0.0f;
    }
}

__global__ __launch_bounds__(256) void k_lnorm(const float* __restrict__ x) {
    int row = blockIdx.x;
    const float* xr = x + (size_t)row * D_N;
    float s = 0.f, s2 = 0.f;
    for (int d = threadIdx.x; d < D_N; d += 256) {
        float v = xr[d];
        s += v; s2 += v * v;
    }
    __shared__ float sh[34];
    #pragma unroll
    for (int o = 16; o > 0; o >>= 1) {
        s  += __shfl_down_sync(0xffffffffu, s, o);
        s2 += __shfl_down_sync(0xffffffffu, s2, o);
    }
    int w = threadIdx.x >> 5, l = threadIdx.x & 31;
    if (l == 0) { sh[w] = s; sh[8 + w] = s2; }
    __syncthreads();
    if (threadIdx.x == 0) {
        float S = 0.f, S2 = 0.f;
        #pragma unroll
        for (int i = 0; i < 8; i++) { S += sh[i]; S2 += sh[8 + i]; }
        float mu = S / (float)D_N;
        float var = S2 / (float)D_N - mu * mu;
        sh[32] = mu;
        sh[33] = rsqrtf(var + 1e-5f) * rsqrtf((float)D_N);
    }
    __syncthreads();
    float mu = sh[32], sc = sh[33];
    __nv_bfloat16* xo = g_xbf + (size_t)row * D_N;
    for (int d = threadIdx.x; d < D_N; d += 256)
        xo[d] = __float2bfloat16((xr[d] - mu) * sc);
}

// x [B_N, D_N] fp32 -> g_xT [D_N, B_N] bf16
__global__ __launch_bounds__(256) void k_transpose(const float* __restrict__ x) {
    __shared__ float tile[32][33];
    int bk = blockIdx.x * 32;   // over B_N
    int bn = blockIdx.y * 32;   // over D_N
    int tx = threadIdx.x & 31, ty = threadIdx.x >> 5;
    #pragma unroll
    for (int i = 0; i < 32; i += 8)
        tile[ty + i][tx] = x[(size_t)(bk + ty + i) * D_N + bn + tx];
    __syncthreads();
    #pragma unroll
    for (int i = 0; i < 32; i += 8)
        g_xT[(size_t)(bn + ty + i) * B_N + bk + tx] = __float2bfloat16(tile[tx][ty + i]);
}

__global__ void k_recip() {
    int i = blockIdx.x * blockDim.x + threadIdx.x;
    if (i < B_N) g_inv[i] = 1.0f / g_rowsum[i];
}

// ---------------- mma.sync GEMM: C[MxN] = A[M,K] . B[N,K]^T ----------------
// SW128 swizzle in smem: addr = row*128 + ((chunk ^ (row&7))*16), chunk = 16B unit.
// 8 warps: 2 (m) x 4 (n); warp tile 64x32; per k16: 4 A ldsm4 + 2 B ldsm4 + 16 mma.
template<int KTOT, bool EPI1>
__global__ __launch_bounds__(256, 1) void k_mma(const float* __restrict__ x) {
    extern __shared__ char smem[];
    const uint32_t smem_raw = smem_u32(smem);
    const uint32_t tiles0 = (smem_raw + 1023u) & ~1023u;
    const int t = threadIdx.x;
    const int wid = t >> 5, lane = t & 31;
    const int bm = blockIdx.y, bn = blockIdx.x;
    const int KC = KTOT / BKS;

    const __nv_bfloat16* A  = EPI1 ? g_xbf : g_expSbf;
    const __nv_bfloat16* Bm = EPI1 ? g_xbf : g_xT;

    const int warp_m0 = (wid >> 2) * 64;
    const int warp_n0 = (wid & 3) * 32;
    const int rowA0 = bm * BT;
    const int rowB0 = bn * BT;

    uint32_t sA[STAGES], sB[STAGES];
    #pragma unroll
    for (int s = 0; s < STAGES; s++) {
        sA[s] = tiles0 + (uint32_t)s * STAGE_B;
        sB[s] = sA[s] + A_TILE_B;
    }

    const int lr0 = t >> 3;      // 0..31
    const int cc = t & 7;        // 16B chunk in 128B row

    #define LOAD_STAGE(sidx, k0elem) do {                                              \
        _Pragma("unroll")                                                              \
        for (int _i = 0; _i < 4; _i++) {                                               \
            int _lr = lr0 + _i * 32;                                                   \
            uint32_t _soff = (uint32_t)(_lr * 128 + ((cc ^ (_lr & 7)) * 16));          \
            cp16(sA[sidx] + _soff, A  + (size_t)(rowA0 + _lr) * KTOT + (k0elem) + cc * 8); \
            cp16(sB[sidx] + _soff, Bm + (size_t)(rowB0 + _lr) * KTOT + (k0elem) + cc * 8); \
        }                                                                              \
    } while (0)

    #pragma unroll
    for (int p = 0; p < STAGES - 1; p++) {
        LOAD_STAGE(p, p * BKS);
        cp_commit();
    }

    float acc[4][4][4];
    #pragma unroll
    for (int i = 0; i < 4; i++)
        #pragma unroll
        for (int j = 0; j < 4; j++)
            #pragma unroll
            for (int r = 0; r < 4; r++) acc[i][j][r] = 0.f;

    // per-thread ldmatrix row components
    const int lrow = lane & 15;      // row within 16-block
    const int lhal = lane >> 4;      // 0/1 -> k half (chunk offset)

    for (int c = 0; c < KC; c++) {
        cp_wait1();
        __syncthreads();
        if (c + STAGES - 1 < KC) LOAD_STAGE((c + STAGES - 1) % STAGES, (c + STAGES - 1) * BKS);
        cp_commit();

        const uint32_t bufA = sA[c % STAGES];
        const uint32_t bufB = sB[c % STAGES];
        #pragma unroll
        for (int kk = 0; kk < 4; kk++) {
            const int chnk = kk * 2 + lhal;
            uint32_t a[4][4], b[2][4];
            #pragma unroll
            for (int im = 0; im < 4; im++) {
                int r = warp_m0 + im * 16 + lrow;
                ldsm4(a[im], bufA + (uint32_t)(r * 128 + ((chnk ^ (r & 7)) * 16)));
            }
            #pragma unroll
            for (int ib = 0; ib < 2; ib++) {
                int r = warp_n0 + ib * 16 + lrow;
                ldsm4(b[ib], bufB + (uint32_t)(r * 128 + ((chnk ^ (r & 7)) * 16)));
            }
            #pragma unroll
            for (int im = 0; im < 4; im++) {
                #pragma unroll
                for (int ib = 0; ib < 2; ib++) {
                    mma_bf16(acc[im][ib * 2 + 0], a[im], b[ib][0], b[ib][2]);
                    mma_bf16(acc[im][ib * 2 + 1], a[im], b[ib][1], b[ib][3]);
                }
            }
        }
        __syncthreads();
    }

    // ---- epilogue ----
    // acc[im][j][{c0,c1,c2,c3}]: c0/c1 -> row lq, cols col,col+1 ; c2/c3 -> row lq+8
    const int lq = lane >> 2;       // row within 8
    const int lp = lane & 3;        // col pair index
    int colg[4];
    #pragma unroll
    for (int j = 0; j < 4; j++)
        colg[j] = rowB0 + warp_n0 + (j >> 1) * 16 + (j & 1) * 8 + 2 * lp;

    if (EPI1) {
        float kp0[4], kp1[4];
        #pragma unroll
        for (int j = 0; j < 4; j++) { kp0[j] = g_keep[colg[j]]; kp1[j] = g_keep[colg[j] + 1]; }
        #pragma unroll
        for (int im = 0; im < 4; im++) {
            #pragma unroll
            for (int h = 0; h < 2; h++) {
                int row = rowA0 + warp_m0 + im * 16 + h * 8 + lq;
                float rs = 0.f;
                #pragma unroll
                for (int j = 0; j < 4; j++) {
                    float w0 = (colg[j] == row) ? 0.f : kp0[j];
                    float w1 = (colg[j] + 1 == row) ? 0.f : kp1[j];
                    float v0 = w0 * __expf(acc[im][j][2 * h + 0]);
                    float v1 = w1 * __expf(acc[im][j][2 * h + 1]);
                    __nv_bfloat16 b0 = __float2bfloat16(v0);
                    __nv_bfloat16 b1 = __float2bfloat16(v1);
                    rs += __bfloat162float(b0) + __bfloat162float(b1);
                    __nv_bfloat162 p2(b0, b1);
                    *reinterpret_cast<uint32_t*>(g_expSbf + (size_t)row * B_N + colg[j]) =
                        *reinterpret_cast<uint32_t*>(&p2);
                }
                rs += __shfl_xor_sync(0xffffffffu, rs, 1);
                rs += __shfl_xor_sync(0xffffffffu, rs, 2);
                if (lp == 0) atomicAdd(&g_rowsum[row], rs);
            }
        }
    } else {
        #pragma unroll
        for (int im = 0; im < 4; im++) {
            #pragma unroll
            for (int h = 0; h < 2; h++) {
                int row = rowA0 + warp_m0 + im * 16 + h * 8 + lq;
                float s1 = g_inv[row] * g_contrib[row];
                float s2 = 1.0f - g_contrib[row];
                #pragma unroll
                for (int j = 0; j < 4; j++) {
                    const float2 xv = *(const float2*)(x + (size_t)row * D_N + colg[j]);
                    float2 o;
                    o.x = acc[im][j][2 * h + 0] * s1 + xv.x * s2;
                    o.y = acc[im][j][2 * h + 1] * s1 + xv.y * s2;
                    *(float2*)(g_R + (size_t)row * D_N + colg[j]) = o;
                }
            }
        }
    }
    #undef LOAD_STAGE
}

// ---------------- mix kernels ----------------
__global__ __launch_bounds__(256) void k_mixx(const float* __restrict__ alpha,
                                              const int* __restrict__ beta,
                                              float* __restrict__ out) {
    int idx = blockIdx.x * blockDim.x + threadIdx.x;
    const int nd4 = D_N / 4;
    if (idx < B_N * nd4) {
        int i = idx / nd4;
        int d4 = idx - i * nd4;
        float a = alpha[i];
        float na = 1.0f - a;
        int bi = beta[i];
        const float4* R4 = (const float4*)g_R;
        float4 r1 = R4[(size_t)i * nd4 + d4];
        float4 r2 = R4[(size_t)bi * nd4 + d4];
        float4 o;
        o.x = a * r1.x + na * r2.x;
        o.y = a * r1.y + na * r2.y;
        o.z = a * r1.z + na * r2.z;
        o.w = a * r1.w + na * r2.w;
        ((float4*)out)[idx] = o;
    }
}

__global__ void k_mixy(const float* __restrict__ alpha,
                       const int* __restrict__ beta,
                       const int* __restrict__ y,
                       float* __restrict__ out) {
    int idx = blockIdx.x * blockDim.x + threadIdx.x;
    if (idx < B_N * C_N) {
        int i = idx / C_N;
        int k = idx - i * C_N;
        float a = alpha[i];
        int bi = beta[i];
        float v = a * (k == y[i] ? 1.0f : 0.0f) + (1.0f - a) * (k == y[bi] ? 1.0f : 0.0f);
        out[(size_t)B_N * D_N + idx] = v;
    }
}

extern "C" void kernel_launch(void* const* d_in, const int* in_sizes, int n_in,
                              void* d_out, int out_size) {
    const float* x     = (const float*)d_in[0];
    const int*   y     = (const int*)  d_in[1];
    const float* alpha = (const float*)d_in[2];
    const int*   beta  = (const int*)  d_in[3];
    const float* c     = (const float*)d_in[4];
    const int*   fs    = (const int*)  d_in[5];
    float* out = (float*)d_out;

    cudaFuncSetAttribute(k_mma<D_N, true>,  cudaFuncAttributeMaxDynamicSharedMemorySize, SMEM_TOTAL);
    cudaFuncSetAttribute(k_mma<B_N, false>, cudaFuncAttributeMaxDynamicSharedMemorySize, SMEM_TOTAL);

    k_prep<<<(B_N + 255) / 256, 256>>>(y, c, fs);
    k_lnorm<<<B_N, 256>>>(x);
    k_transpose<<<dim3(B_N / 32, D_N / 32), 256>>>(x);

    // GEMM1: S = Xn.Xn^T (M=N=4096, K=2048), fused mask+exp+rowsum
    k_mma<D_N, true><<<dim3(B_N / BT, B_N / BT), 256, SMEM_TOTAL>>>(nullptr);
    k_recip<<<(B_N + 255) / 256, 256>>>();
    // GEMM2: recon = expS . x (M=4096, N=2048, K=4096), fused normalize+blend
    k_mma<B_N, false><<<dim3(D_N / BT, B_N / BT), 256, SMEM_TOTAL>>>(x);

    k_mixx<<<(B_N * (D_N / 4) + 255) / 256, 256>>>(alpha, beta, out);
    k_mixy<<<(B_N * C_N + 255) / 256, 256>>>(alpha, beta, y, out);
}